// round 8
// baseline (speedup 1.0000x reference)
#include <cuda_runtime.h>
#include <cstdint>

#define NN 8192
#define CONV_BLOCKS 128
#define NODES_PER_CB (NN / CONV_BLOCKS)   // 64

// Scratch + progress counters (allocation-free rule: __device__ globals).
// Counters are zero-initialized and reset to zero by the last block every
// launch -> deterministic across graph replays.
__device__ float g_conv[NN];
__device__ float g_h[NN];
__device__ int g_c1;   // conv sub-blocks finished (0..128)
__device__ int g_c2;   // layer-1 rows finished   (0..8192)
__device__ int g_c3;   // blocks retired          (0..16384), last one resets

__device__ __forceinline__ void cp_async16(uint32_t smem_addr, const void* gptr) {
    asm volatile("cp.async.cg.shared.global [%0], [%1], 16;\n"
                 :: "r"(smem_addr), "l"(gptr));
}
__device__ __forceinline__ void cp_commit() {
    asm volatile("cp.async.commit_group;\n");
}
template <int N>
__device__ __forceinline__ void cp_wait() {
    asm volatile("cp.async.wait_group %0;\n" :: "n"(N));
}

__global__ void __launch_bounds__(256, 6) fused_mlp_kernel(
    const float* __restrict__ nf,
    const float* __restrict__ cw,
    const float* __restrict__ cb,
    const float* __restrict__ W1,
    const float* __restrict__ b1,
    const float* __restrict__ W2,
    const float* __restrict__ b2,
    float* __restrict__ out) {
    __shared__ float4 buf[NN / 4];  // 32 KB W row
    __shared__ float red[8];

    const int bid = blockIdx.x;
    const int tid = threadIdx.x;
    const bool phase2 = (bid >= NN);
    const int row = phase2 ? (bid - NN) : bid;

    const float* __restrict__ W    = phase2 ? W2 : W1;
    const float* __restrict__ bias = phase2 ? b2 : b1;
    const float4* __restrict__ W4  =
        reinterpret_cast<const float4*>(W + (size_t)row * NN);

    const uint32_t sbase = (uint32_t)__cvta_generic_to_shared(buf);

    // Kick off the whole 32KB W-row copy immediately (overlaps with conv /
    // previous-phase compute while this block waits on its dependency).
    #pragma unroll
    for (int j = 0; j < 4; ++j) {
        int i = tid + 256 * j;
        cp_async16(sbase + i * 16, W4 + i);
    }
    cp_commit();
    #pragma unroll
    for (int j = 4; j < 8; ++j) {
        int i = tid + 256 * j;
        cp_async16(sbase + i * 16, W4 + i);
    }
    cp_commit();

    if (!phase2) {
        // ---- conv + sigmoid, computed by the first 128 blocks (wave-1 resident) ----
        if (bid < CONV_BLOCKS) {
            if (tid < NODES_PER_CB) {
                const int i = bid * NODES_PER_CB + tid;
                const float4* nrow = reinterpret_cast<const float4*>(nf + (size_t)i * 16);
                float4 w0 = reinterpret_cast<const float4*>(cw)[0];
                float4 w1 = reinterpret_cast<const float4*>(cw)[1];
                float4 w2 = reinterpret_cast<const float4*>(cw)[2];
                float4 w3 = reinterpret_cast<const float4*>(cw)[3];
                float4 a0 = nrow[0], a1 = nrow[1], a2 = nrow[2], a3 = nrow[3];
                float s = a0.x*w0.x + a0.y*w0.y + a0.z*w0.z + a0.w*w0.w
                        + a1.x*w1.x + a1.y*w1.y + a1.z*w1.z + a1.w*w1.w
                        + a2.x*w2.x + a2.y*w2.y + a2.z*w2.z + a2.w*w2.w
                        + a3.x*w3.x + a3.y*w3.y + a3.z*w3.z + a3.w*w3.w;
                s += cb[0];
                g_conv[i] = 1.0f / (1.0f + __expf(-s));
            }
            __syncthreads();
            if (tid == 0) {
                __threadfence();
                atomicAdd(&g_c1, 1);
            }
        }
        // Wait until the full conv vector is published
        if (tid == 0) {
            while (*(volatile int*)&g_c1 < CONV_BLOCKS) __nanosleep(64);
            __threadfence();
        }
        __syncthreads();
    } else {
        // Wait until all layer-1 rows are published
        if (tid == 0) {
            while (*(volatile int*)&g_c2 < NN) __nanosleep(128);
            __threadfence();
        }
        __syncthreads();
    }

    // ---- dot(W_row, x): W from shared (cp.async), x via L2 (__ldcg) ----
    const float4* __restrict__ x4 = phase2
        ? reinterpret_cast<const float4*>(g_h)
        : reinterpret_cast<const float4*>(g_conv);

    float s = 0.0f;
    cp_wait<1>();
    #pragma unroll
    for (int j = 0; j < 4; ++j) {
        int i = tid + 256 * j;
        float4 a = buf[i];
        float4 v = __ldcg(x4 + i);
        s += a.x * v.x + a.y * v.y + a.z * v.z + a.w * v.w;
    }
    cp_wait<0>();
    #pragma unroll
    for (int j = 4; j < 8; ++j) {
        int i = tid + 256 * j;
        float4 a = buf[i];
        float4 v = __ldcg(x4 + i);
        s += a.x * v.x + a.y * v.y + a.z * v.z + a.w * v.w;
    }

    // Block reduction
    #pragma unroll
    for (int o = 16; o > 0; o >>= 1) s += __shfl_xor_sync(0xffffffffu, s, o);
    if ((tid & 31) == 0) red[tid >> 5] = s;
    __syncthreads();

    if (tid == 0) {
        float t = 0.0f;
        #pragma unroll
        for (int w = 0; w < 8; ++w) t += red[w];
        t += bias[row];
        if (phase2) {
            out[row] = t;
        } else {
            g_h[row] = tanhf(t);
            __threadfence();
            atomicAdd(&g_c2, 1);
        }
        // Retirement counting + counter reset for graph-replay determinism
        int prev = atomicAdd(&g_c3, 1);
        if (prev == 2 * NN - 1) {
            g_c1 = 0;
            g_c2 = 0;
            __threadfence();
            g_c3 = 0;
        }
    }
}

extern "C" void kernel_launch(void* const* d_in, const int* in_sizes, int n_in,
                              void* d_out, int out_size) {
    const float* node_features = (const float*)d_in[0]; // (8192, 16)
    const float* conv_w        = (const float*)d_in[1]; // (16,)
    const float* conv_b        = (const float*)d_in[2]; // scalar
    const float* W1            = (const float*)d_in[3]; // (8192, 8192)
    const float* b1            = (const float*)d_in[4]; // (8192,)
    const float* W2            = (const float*)d_in[5]; // (8192, 8192)
    const float* b2            = (const float*)d_in[6]; // (8192,)
    float* out = (float*)d_out;

    fused_mlp_kernel<<<2 * NN, 256>>>(node_features, conv_w, conv_b,
                                      W1, b1, W2, b2, out);
}

// round 9
// speedup vs baseline: 1.1441x; 1.1441x over previous
#include <cuda_runtime.h>
#include <cstdint>

#define NN 8192
#define CONV_BLOCKS 128
#define NODES_PER_CB (NN / CONV_BLOCKS)   // 64

// Scratch + progress counters (allocation-free rule: __device__ globals).
// Zero-initialized; reset to zero by the last retiring block of kernel A
// every launch -> deterministic across graph replays.
__device__ float g_conv[NN];
__device__ float g_h[NN];
__device__ int g_c1;    // conv sub-blocks finished (0..128)
__device__ int g_ret;   // kernel-A blocks retired  (0..8192), last resets

__device__ __forceinline__ void cp_async16(uint32_t smem_addr, const void* gptr) {
    asm volatile("cp.async.cg.shared.global [%0], [%1], 16;\n"
                 :: "r"(smem_addr), "l"(gptr));
}
__device__ __forceinline__ void cp_commit() {
    asm volatile("cp.async.commit_group;\n");
}
template <int N>
__device__ __forceinline__ void cp_wait() {
    asm volatile("cp.async.wait_group %0;\n" :: "n"(N));
}

// Kernel A: conv+sigmoid (blocks 0..127) fused with layer-1 matvec (all 8192
// blocks, one row each). Every block first queues its whole 32KB W1 row via
// cp.async (zero register cost), so the conv-wait spin is hidden under the
// weight stream.
__global__ void __launch_bounds__(256) layer1_kernel(
    const float* __restrict__ nf,
    const float* __restrict__ cw,
    const float* __restrict__ cb,
    const float* __restrict__ W1,
    const float* __restrict__ b1) {
    __shared__ float4 buf[NN / 4];  // 32 KB
    __shared__ float red[8];

    const int row = blockIdx.x;
    const int tid = threadIdx.x;
    const float4* __restrict__ W4 =
        reinterpret_cast<const float4*>(W1 + (size_t)row * NN);
    const uint32_t sbase = (uint32_t)__cvta_generic_to_shared(buf);

    // Queue the full W row copy first (overlaps conv + spin).
    #pragma unroll
    for (int j = 0; j < 4; ++j) {
        int i = tid + 256 * j;
        cp_async16(sbase + i * 16, W4 + i);
    }
    cp_commit();
    #pragma unroll
    for (int j = 4; j < 8; ++j) {
        int i = tid + 256 * j;
        cp_async16(sbase + i * 16, W4 + i);
    }
    cp_commit();

    // Conv producers: first 128 blocks (guaranteed wave-1 resident).
    if (row < CONV_BLOCKS) {
        if (tid < NODES_PER_CB) {
            const int i = row * NODES_PER_CB + tid;
            const float4* nrow = reinterpret_cast<const float4*>(nf + (size_t)i * 16);
            float4 w0 = reinterpret_cast<const float4*>(cw)[0];
            float4 w1 = reinterpret_cast<const float4*>(cw)[1];
            float4 w2 = reinterpret_cast<const float4*>(cw)[2];
            float4 w3 = reinterpret_cast<const float4*>(cw)[3];
            float4 a0 = nrow[0], a1 = nrow[1], a2 = nrow[2], a3 = nrow[3];
            float s = a0.x*w0.x + a0.y*w0.y + a0.z*w0.z + a0.w*w0.w
                    + a1.x*w1.x + a1.y*w1.y + a1.z*w1.z + a1.w*w1.w
                    + a2.x*w2.x + a2.y*w2.y + a2.z*w2.z + a2.w*w2.w
                    + a3.x*w3.x + a3.y*w3.y + a3.z*w3.z + a3.w*w3.w;
            s += cb[0];
            g_conv[i] = 1.0f / (1.0f + __expf(-s));
        }
        __syncthreads();
        if (tid == 0) {
            __threadfence();
            atomicAdd(&g_c1, 1);
        }
    }

    // Wait for the full conv vector (hidden under the cp.async stream).
    if (tid == 0) {
        while (*(volatile int*)&g_c1 < CONV_BLOCKS) __nanosleep(32);
        __threadfence();
    }
    __syncthreads();

    const float4* __restrict__ x4 = reinterpret_cast<const float4*>(g_conv);

    float s = 0.0f;
    cp_wait<1>();
    #pragma unroll
    for (int j = 0; j < 4; ++j) {
        int i = tid + 256 * j;
        float4 a = buf[i];
        float4 v = __ldcg(x4 + i);   // cross-CTA produced -> L2
        s += a.x * v.x + a.y * v.y + a.z * v.z + a.w * v.w;
    }
    cp_wait<0>();
    #pragma unroll
    for (int j = 4; j < 8; ++j) {
        int i = tid + 256 * j;
        float4 a = buf[i];
        float4 v = __ldcg(x4 + i);
        s += a.x * v.x + a.y * v.y + a.z * v.z + a.w * v.w;
    }

    #pragma unroll
    for (int o = 16; o > 0; o >>= 1) s += __shfl_xor_sync(0xffffffffu, s, o);
    if ((tid & 31) == 0) red[tid >> 5] = s;
    __syncthreads();
    if (tid == 0) {
        float t = 0.0f;
        #pragma unroll
        for (int w = 0; w < 8; ++w) t += red[w];
        g_h[row] = tanhf(t + b1[row]);
        // Counter reset for graph-replay determinism.
        int prev = atomicAdd(&g_ret, 1);
        if (prev == NN - 1) {
            g_c1 = 0;
            __threadfence();
            g_ret = 0;
        }
    }
}

// Kernel B: layer-2 matvec (identical to the proven R6 kernel).
__global__ void __launch_bounds__(256) layer2_kernel(
    const float* __restrict__ W,
    const float* __restrict__ b,
    const float* __restrict__ x,
    float* __restrict__ y) {
    __shared__ float4 buf[NN / 4];
    __shared__ float red[8];

    const int row = blockIdx.x;
    const int tid = threadIdx.x;
    const float4* __restrict__ W4 = reinterpret_cast<const float4*>(W + (size_t)row * NN);
    const float4* __restrict__ x4 = reinterpret_cast<const float4*>(x);
    const uint32_t sbase = (uint32_t)__cvta_generic_to_shared(buf);

    #pragma unroll
    for (int j = 0; j < 4; ++j) {
        int i = tid + 256 * j;
        cp_async16(sbase + i * 16, W4 + i);
    }
    cp_commit();
    #pragma unroll
    for (int j = 4; j < 8; ++j) {
        int i = tid + 256 * j;
        cp_async16(sbase + i * 16, W4 + i);
    }
    cp_commit();

    float s = 0.0f;
    cp_wait<1>();
    #pragma unroll
    for (int j = 0; j < 4; ++j) {
        int i = tid + 256 * j;
        float4 a = buf[i];
        float4 v = x4[i];
        s += a.x * v.x + a.y * v.y + a.z * v.z + a.w * v.w;
    }
    cp_wait<0>();
    #pragma unroll
    for (int j = 4; j < 8; ++j) {
        int i = tid + 256 * j;
        float4 a = buf[i];
        float4 v = x4[i];
        s += a.x * v.x + a.y * v.y + a.z * v.z + a.w * v.w;
    }

    #pragma unroll
    for (int o = 16; o > 0; o >>= 1) s += __shfl_xor_sync(0xffffffffu, s, o);
    if ((tid & 31) == 0) red[tid >> 5] = s;
    __syncthreads();
    if (tid < 8) {
        s = red[tid];
        #pragma unroll
        for (int o = 4; o > 0; o >>= 1) s += __shfl_xor_sync(0x000000ffu, s, o);
        if (tid == 0) y[row] = s + b[row];
    }
}

extern "C" void kernel_launch(void* const* d_in, const int* in_sizes, int n_in,
                              void* d_out, int out_size) {
    const float* node_features = (const float*)d_in[0]; // (8192, 16)
    const float* conv_w        = (const float*)d_in[1]; // (16,)
    const float* conv_b        = (const float*)d_in[2]; // scalar
    const float* W1            = (const float*)d_in[3]; // (8192, 8192)
    const float* b1            = (const float*)d_in[4]; // (8192,)
    const float* W2            = (const float*)d_in[5]; // (8192, 8192)
    const float* b2            = (const float*)d_in[6]; // (8192,)
    float* out = (float*)d_out;

    float* h;
    cudaGetSymbolAddress((void**)&h, g_h);

    layer1_kernel<<<NN, 256>>>(node_features, conv_w, conv_b, W1, b1);
    layer2_kernel<<<NN, 256>>>(W2, b2, h, out);
}